// round 13
// baseline (speedup 1.0000x reference)
#include <cuda_runtime.h>
#include <cuda_fp16.h>
#include <math.h>
#include <stdint.h>

// ---------------- problem constants ----------------
#define NROWS   253952      // B*S*N = 16*512*31
#define DM      256
#define VOC     64
#define NN      31
#define VE      4096
#define NTOK    8192        // B*S
#define TILE_M  64
#define GRID_M  (NROWS / TILE_M)   // 3968
#define NT      256

// ---------------- smem layout: main kernel ----------------
#define XPB     528           // activation row pitch (33*16 -> conflict-free ldsm)
#define W2PB    528           // stage-2 weight chunk pitch (256 cols + pad)
#define WPB     144           // Wo row pitch (9*16)
#define SLOTSZ  36864         // max(64*528=33792, 256*144=36864)

#define SM_X    0             // 64*528 = 33792 (P0 @0, P1 @16384 after stage-2)
#define SM_W    33792         // slot0 33792..70656, slot1 70656..107520
#define SM_ST   107520        // float2[512] = 4096
#define SMEM_BYTES 111616     // 2 CTAs/SM (223232 <= 228KB)

// partial-logits regions (fp32 [64 rows][64 vocab] per n_grp)
#define P_OFF0  0             // n_grp 0
#define P_OFF1  16384         // n_grp 1
#define P_OFF2  70656         // n_grp 2 (slot1, dead after kc3)
#define P_OFF3  87040         // n_grp 3

// ---------------- smem layout: prep_FGM ----------------
#define PF_SMA  0
#define PF_SMW  33792
#define PF_SMF  70656
#define PF_SMEM 104448

// ---------------- prepped device globals ----------------
__device__ __align__(16) __half g_wf[65536];        // Wf fp16  [k][n]
__device__ __align__(16) __half g_w1g[65536];       // lg[k]*W1 [k][n]
__device__ __align__(16) __half g_w2g[65536];       // lg[k]*W2 [k][n]
__device__ __align__(16) __half g_wo[16384];        // W_out    [k][64]
__device__ __align__(16) __half g_F[VE * 256];      // F[e] = gelu(emb[e]@Wf + bf)
__device__ __align__(16) __half g_G1h[VE * 256];    // F[e] @ W1g   (fp16)
__device__ __align__(16) __half g_M1h[NTOK * 256];  // mh[tok] @ W1g (fp16)
__device__ __align__(16) __half g_mh[NTOK * 256];   // fp16 memory copy
__device__ __align__(16) float2 g_SF[VE];           // (sum F, sum F^2)
__device__ __align__(16) float2 g_SM[NTOK];         // (sum mh, sum mh^2)
__device__ float g_d1[256], g_e1[256], g_d2[256], g_e2[256];

// ---------------- PTX helpers ----------------
__device__ __forceinline__ uint32_t smem_u32_of(const void* p) {
    uint32_t a;
    asm("{ .reg .u64 t; cvta.to.shared.u64 t, %1; cvt.u32.u64 %0, t; }" : "=r"(a) : "l"(p));
    return a;
}
__device__ __forceinline__ void ldsm_x4(uint32_t* r, uint32_t addr) {
    asm volatile("ldmatrix.sync.aligned.m8n8.x4.shared.b16 {%0,%1,%2,%3}, [%4];"
        : "=r"(r[0]), "=r"(r[1]), "=r"(r[2]), "=r"(r[3]) : "r"(addr));
}
__device__ __forceinline__ void ldsm_x4_t(uint32_t* r, uint32_t addr) {
    asm volatile("ldmatrix.sync.aligned.m8n8.x4.trans.shared.b16 {%0,%1,%2,%3}, [%4];"
        : "=r"(r[0]), "=r"(r[1]), "=r"(r[2]), "=r"(r[3]) : "r"(addr));
}
__device__ __forceinline__ void mma16816(float* d, const uint32_t* a, const uint32_t* b) {
    asm volatile("mma.sync.aligned.m16n8k16.row.col.f32.f16.f16.f32 "
        "{%0,%1,%2,%3}, {%4,%5,%6,%7}, {%8,%9}, {%0,%1,%2,%3};"
        : "+f"(d[0]), "+f"(d[1]), "+f"(d[2]), "+f"(d[3])
        : "r"(a[0]), "r"(a[1]), "r"(a[2]), "r"(a[3]), "r"(b[0]), "r"(b[1]));
}
#define CP_ASYNC16(dst, src) \
    asm volatile("cp.async.cg.shared.global [%0], [%1], 16;" :: "r"(dst), "l"(src) : "memory")
#define CP_COMMIT() asm volatile("cp.async.commit_group;" ::: "memory")
#define CP_WAIT0()  asm volatile("cp.async.wait_group 0;" ::: "memory")

// ---------------- math helpers ----------------
__device__ __forceinline__ float gelu_exact(float x) {
    return 0.5f * x * (1.0f + erff(x * 0.70710678118654752f));
}
__device__ __forceinline__ uint32_t pk(float a, float b) {
    __half2 h = __floats2half2_rn(a, b);
    return *reinterpret_cast<uint32_t*>(&h);
}
__device__ __forceinline__ float2 unpk(uint32_t u) {
    __half2 h = *reinterpret_cast<__half2*>(&u);
    return __half22float2(h);
}

// ---------------- prep: weights ----------------
__global__ void prep_weights(const float* __restrict__ Wf, const float* __restrict__ W1,
                             const float* __restrict__ W2, const float* __restrict__ Wo,
                             const float* __restrict__ lg) {
    int idx = blockIdx.x * blockDim.x + threadIdx.x;   // 832*256
    if (idx < 65536) {
        g_wf[idx] = __float2half_rn(Wf[idx]);
    } else if (idx < 131072) {
        int e = idx - 65536;
        g_w1g[e] = __float2half_rn(lg[e >> 8] * W1[e]);
    } else if (idx < 196608) {
        int e = idx - 131072;
        g_w2g[e] = __float2half_rn(lg[e >> 8] * W2[e]);
    } else {
        int e = idx - 196608;
        g_wo[e] = __float2half_rn(Wo[e]);
    }
}

// parallel prep_vecs: grid 8 x 256; n = blk*32 + tid/8, k split 8-way, shfl reduce
__global__ void prep_vecs(const float* __restrict__ W1, const float* __restrict__ b1,
                          const float* __restrict__ W2, const float* __restrict__ b2,
                          const float* __restrict__ lg, const float* __restrict__ lb) {
    const int tid = threadIdx.x;
    const int n  = blockIdx.x * 32 + (tid >> 3);
    const int ks = tid & 7;
    float d1 = 0.f, e1 = 0.f, d2 = 0.f, e2 = 0.f;
    for (int k = ks * 32; k < ks * 32 + 32; k++) {
        float g = lg[k], b = lb[k];
        float w1 = W1[k * 256 + n], w2 = W2[k * 256 + n];
        d1 += g * w1; e1 += b * w1;
        d2 += g * w2; e2 += b * w2;
    }
    #pragma unroll
    for (int off = 1; off <= 4; off <<= 1) {
        d1 += __shfl_xor_sync(0xffffffffu, d1, off);
        e1 += __shfl_xor_sync(0xffffffffu, e1, off);
        d2 += __shfl_xor_sync(0xffffffffu, d2, off);
        e2 += __shfl_xor_sync(0xffffffffu, e2, off);
    }
    if (ks == 0) {
        g_d1[n] = d1; g_e1[n] = e1 + b1[n];
        g_d2[n] = d2; g_e2[n] = e2 + b2[n];
    }
}

// ---------------- prep_FGM (verified R11/R12) ----------------
__global__ void __launch_bounds__(256, 1)
prep_FGM(const float* __restrict__ emb, const float* __restrict__ memory,
         const float* __restrict__ bf)
{
    extern __shared__ __align__(16) uint8_t sm[];
    const int tid = threadIdx.x, wid = tid >> 5, lane = tid & 31;
    const bool fpath = (blockIdx.x < 64);
    const int row0 = fpath ? blockIdx.x * 64 : (blockIdx.x - 64) * 64;
    const float* A = fpath ? (emb + (size_t)row0 * 256) : (memory + (size_t)row0 * 256);
    const uint32_t smb = smem_u32_of(sm);

    for (int q = tid; q < 64 * 8; q += 256) {
        int row = q >> 3, c32 = (q & 7) << 5;
        const float4* src = (const float4*)(A + (size_t)row * 256 + c32);
        uint4* dst = (uint4*)(sm + PF_SMA + (uint32_t)row * XPB + c32 * 2);
        #pragma unroll
        for (int u = 0; u < 4; u++) {
            float4 f0 = __ldg(src + 2 * u);
            float4 f1 = __ldg(src + 2 * u + 1);
            uint4 p;
            p.x = pk(f0.x, f0.y); p.y = pk(f0.z, f0.w);
            p.z = pk(f1.x, f1.y); p.w = pk(f1.z, f1.w);
            dst[u] = p;
            if (!fpath)
                *(uint4*)(g_mh + (size_t)(row0 + row) * 256 + c32 + u * 8) = p;
        }
    }

    const int m_grp = wid >> 1, n_grp = wid & 1;
    const __half* W1p = fpath ? g_wf : g_w1g;

    for (int j0 = 0; j0 < 256; j0 += 64) {
        __syncthreads();
        #pragma unroll
        for (int i = tid; i < 2048; i += 256) {
            int k = i >> 3, c = i & 7;
            CP_ASYNC16(smb + PF_SMW + k * 144 + (c << 4),
                       (const uint8_t*)(W1p + (size_t)k * 256 + j0) + (c << 4));
        }
        CP_COMMIT();
        CP_WAIT0();
        __syncthreads();

        const uint32_t a_addr = smb + PF_SMA + (uint32_t)(m_grp * 16 + (lane & 15)) * XPB + ((lane >> 4) << 4);
        const uint32_t b_addr = smb + PF_SMW + (uint32_t)(lane & 15) * 144 + ((lane >> 4) << 4) + n_grp * 64;
        float acc[4][4] = {};
        #pragma unroll
        for (int k0 = 0; k0 < 256; k0 += 16) {
            uint32_t Ar[4], B0[4], B1[4];
            ldsm_x4(Ar, a_addr + k0 * 2);
            ldsm_x4_t(B0, b_addr + (uint32_t)k0 * 144);
            ldsm_x4_t(B1, b_addr + (uint32_t)k0 * 144 + 32);
            mma16816(acc[0], Ar, B0); mma16816(acc[1], Ar, B0 + 2);
            mma16816(acc[2], Ar, B1); mma16816(acc[3], Ar, B1 + 2);
        }
        const int rlo = m_grp * 16 + (lane >> 2), rhi = rlo + 8;
        #pragma unroll
        for (int v = 0; v < 4; v++) {
            const int col = j0 + n_grp * 32 + v * 8 + 2 * (lane & 3);
            if (fpath) {
                float b0 = __ldg(bf + col), b1v = __ldg(bf + col + 1);
                uint32_t plo = pk(gelu_exact(acc[v][0] + b0), gelu_exact(acc[v][1] + b1v));
                uint32_t phi = pk(gelu_exact(acc[v][2] + b0), gelu_exact(acc[v][3] + b1v));
                *(uint32_t*)(g_F + (size_t)(row0 + rlo) * 256 + col) = plo;
                *(uint32_t*)(g_F + (size_t)(row0 + rhi) * 256 + col) = phi;
                *(uint32_t*)(sm + PF_SMF + (uint32_t)rlo * XPB + col * 2) = plo;
                *(uint32_t*)(sm + PF_SMF + (uint32_t)rhi * XPB + col * 2) = phi;
            } else {
                *(uint32_t*)(g_M1h + (size_t)(row0 + rlo) * 256 + col) = pk(acc[v][0], acc[v][1]);
                *(uint32_t*)(g_M1h + (size_t)(row0 + rhi) * 256 + col) = pk(acc[v][2], acc[v][3]);
            }
        }
    }
    __syncthreads();

    {
        const int rr = tid >> 2, qq = tid & 3;
        const uint32_t base = fpath ? PF_SMF : PF_SMA;
        const uint4* rp = (const uint4*)(sm + base + (uint32_t)rr * XPB + qq * 128);
        float s1 = 0.f, s2 = 0.f;
        #pragma unroll
        for (int u = 0; u < 8; u++) {
            uint4 v = rp[u];
            float2 a0 = unpk(v.x), a1 = unpk(v.y), a2 = unpk(v.z), a3 = unpk(v.w);
            s1 += (a0.x + a0.y) + (a1.x + a1.y) + (a2.x + a2.y) + (a3.x + a3.y);
            s2 += a0.x*a0.x + a0.y*a0.y + a1.x*a1.x + a1.y*a1.y
                + a2.x*a2.x + a2.y*a2.y + a3.x*a3.x + a3.y*a3.y;
        }
        s1 += __shfl_xor_sync(0xffffffffu, s1, 1);
        s2 += __shfl_xor_sync(0xffffffffu, s2, 1);
        s1 += __shfl_xor_sync(0xffffffffu, s1, 2);
        s2 += __shfl_xor_sync(0xffffffffu, s2, 2);
        if (qq == 0) {
            if (fpath) g_SF[row0 + rr] = make_float2(s1, s2);
            else       g_SM[row0 + rr] = make_float2(s1, s2);
        }
    }
    if (!fpath) return;

    for (int j0 = 0; j0 < 256; j0 += 64) {
        __syncthreads();
        #pragma unroll
        for (int i = tid; i < 2048; i += 256) {
            int k = i >> 3, c = i & 7;
            CP_ASYNC16(smb + PF_SMW + k * 144 + (c << 4),
                       (const uint8_t*)(g_w1g + (size_t)k * 256 + j0) + (c << 4));
        }
        CP_COMMIT();
        CP_WAIT0();
        __syncthreads();

        const uint32_t a_addr = smb + PF_SMF + (uint32_t)(m_grp * 16 + (lane & 15)) * XPB + ((lane >> 4) << 4);
        const uint32_t b_addr = smb + PF_SMW + (uint32_t)(lane & 15) * 144 + ((lane >> 4) << 4) + n_grp * 64;
        float acc[4][4] = {};
        #pragma unroll
        for (int k0 = 0; k0 < 256; k0 += 16) {
            uint32_t Ar[4], B0[4], B1[4];
            ldsm_x4(Ar, a_addr + k0 * 2);
            ldsm_x4_t(B0, b_addr + (uint32_t)k0 * 144);
            ldsm_x4_t(B1, b_addr + (uint32_t)k0 * 144 + 32);
            mma16816(acc[0], Ar, B0); mma16816(acc[1], Ar, B0 + 2);
            mma16816(acc[2], Ar, B1); mma16816(acc[3], Ar, B1 + 2);
        }
        const int rlo = m_grp * 16 + (lane >> 2), rhi = rlo + 8;
        #pragma unroll
        for (int v = 0; v < 4; v++) {
            const int col = j0 + n_grp * 32 + v * 8 + 2 * (lane & 3);
            *(uint32_t*)(g_G1h + (size_t)(row0 + rlo) * 256 + col) = pk(acc[v][0], acc[v][1]);
            *(uint32_t*)(g_G1h + (size_t)(row0 + rhi) * 256 + col) = pk(acc[v][2], acc[v][3]);
        }
    }
}

// ---------------- main kernel: chunk issue ----------------
// h 0..3: W2g K-chunk h (64 k-rows x 256 cols, pitch 528, slot h&1)
// h 4:    full Wo (256 k-rows x 64 cols, pitch 144) into slot0
__device__ __forceinline__ void issue_half(uint32_t smb, int tid, int h) {
    if (h > 4) return;
    uint32_t dst = smb + SM_W + (uint32_t)(h & 1) * SLOTSZ;
    if (h < 4) {
        const __half* src = g_w2g + (size_t)(h * 64) * 256;
        #pragma unroll
        for (int i = tid; i < 2048; i += NT) {          // 64 k-rows x 32 x 16B
            int k = i >> 5, c = i & 31;
            CP_ASYNC16(dst + k * W2PB + (c << 4),
                       (const uint8_t*)(src + (size_t)k * 256) + (c << 4));
        }
    } else {
        #pragma unroll
        for (int i = tid; i < 2048; i += NT) {          // 256 k-rows x 8 x 16B
            int k = i >> 3, c = i & 7;
            CP_ASYNC16(dst + k * WPB + (c << 4),
                       (const uint8_t*)(g_wo + (size_t)k * 64) + (c << 4));
        }
    }
    CP_COMMIT();
}

// ---------------- main fused kernel ----------------
__global__ void __launch_bounds__(NT, 2)
dec_main(const int* __restrict__ fidx, float* __restrict__ out)
{
    extern __shared__ __align__(16) uint8_t sm[];
    const int tid   = threadIdx.x;
    const int wid   = tid >> 5;
    const int lane  = tid & 31;
    const int m_grp = wid & 1;       // 0..1 (32-row block)
    const int n_grp = wid >> 1;      // 0..3 (64-col block)
    const int gr0   = blockIdx.x * TILE_M;
    const uint32_t smb = smem_u32_of(sm);
    float2* stats = (float2*)(sm + SM_ST);

    issue_half(smb, tid, 0);         // first W2g K-chunk in flight

    // ---- fused gather: dot + folded-LN + y1 -> X smem; stats(y1) ----
    const int r = tid >> 2, q = tid & 3;
    const int e = __ldg(fidx + gr0 + r);
    const int tok = (gr0 + r) / NN;
    {
        const uint4* Fp = (const uint4*)(g_F  + (size_t)e   * DM + q * 64);
        const uint4* Mp = (const uint4*)(g_mh + (size_t)tok * DM + q * 64);
        float dot = 0.f;
        #pragma unroll
        for (int u = 0; u < 8; u++) {
            uint4 fv = __ldg(Fp + u);
            uint4 mv = __ldg(Mp + u);
            float2 f0 = unpk(fv.x), f1 = unpk(fv.y), f2 = unpk(fv.z), f3 = unpk(fv.w);
            float2 m0 = unpk(mv.x), m1 = unpk(mv.y), m2 = unpk(mv.z), m3 = unpk(mv.w);
            dot += f0.x*m0.x + f0.y*m0.y + f1.x*m1.x + f1.y*m1.y
                 + f2.x*m2.x + f2.y*m2.y + f3.x*m3.x + f3.y*m3.y;
        }
        dot += __shfl_xor_sync(0xffffffffu, dot, 1);
        dot += __shfl_xor_sync(0xffffffffu, dot, 2);

        float2 sf  = __ldg(&g_SF[e]);
        float2 smv = __ldg(&g_SM[tok]);
        const float s1x = sf.x + smv.x;
        const float s2x = sf.y + smv.y + 2.0f * dot;
        const float mu  = s1x * (1.0f / 256.0f);
        const float rsx = rsqrtf(s2x * (1.0f / 256.0f) - mu * mu + 1e-5f);
        const float nmr = -mu * rsx;

        const uint4* Gp = (const uint4*)(g_G1h + (size_t)e   * DM + q * 64);
        const uint4* Np = (const uint4*)(g_M1h + (size_t)tok * DM + q * 64);
        float s1 = 0.f, s2 = 0.f;
        #pragma unroll
        for (int u = 0; u < 8; u++) {
            const int c = q * 64 + u * 8;
            uint4 gv = __ldg(Gp + u);
            uint4 nv = __ldg(Np + u);
            float2 g0 = unpk(gv.x), g1 = unpk(gv.y), g2 = unpk(gv.z), g3 = unpk(gv.w);
            float2 n0 = unpk(nv.x), n1 = unpk(nv.y), n2 = unpk(nv.z), n3 = unpk(nv.w);
            float4 da = __ldg((const float4*)(g_d1 + c)), db = __ldg((const float4*)(g_d1 + c + 4));
            float4 ea = __ldg((const float4*)(g_e1 + c)), eb = __ldg((const float4*)(g_e1 + c + 4));
            float y0 = gelu_exact(fmaf(rsx, g0.x + n0.x, fmaf(nmr, da.x, ea.x)));
            float y1 = gelu_exact(fmaf(rsx, g0.y + n0.y, fmaf(nmr, da.y, ea.y)));
            float y2 = gelu_exact(fmaf(rsx, g1.x + n1.x, fmaf(nmr, da.z, ea.z)));
            float y3 = gelu_exact(fmaf(rsx, g1.y + n1.y, fmaf(nmr, da.w, ea.w)));
            float y4 = gelu_exact(fmaf(rsx, g2.x + n2.x, fmaf(nmr, db.x, eb.x)));
            float y5 = gelu_exact(fmaf(rsx, g2.y + n2.y, fmaf(nmr, db.y, eb.y)));
            float y6 = gelu_exact(fmaf(rsx, g3.x + n3.x, fmaf(nmr, db.z, eb.z)));
            float y7 = gelu_exact(fmaf(rsx, g3.y + n3.y, fmaf(nmr, db.w, eb.w)));
            s1 += (y0 + y1) + (y2 + y3) + (y4 + y5) + (y6 + y7);
            s2 += y0*y0 + y1*y1 + y2*y2 + y3*y3 + y4*y4 + y5*y5 + y6*y6 + y7*y7;
            uint4 p;
            p.x = pk(y0, y1); p.y = pk(y2, y3); p.z = pk(y4, y5); p.w = pk(y6, y7);
            *(uint4*)(sm + SM_X + (uint32_t)r * XPB + c * 2) = p;
        }
        stats[q * 64 + r] = make_float2(s1, s2);
    }
    __syncthreads();   // X + stats visible

    // ---- per-row LN coefficients for stage 2 ----
    const int rq = lane >> 2;
    float rs[4], mrs[4];
    #pragma unroll
    for (int qq = 0; qq < 4; qq++) {
        int rr = m_grp * 32 + (qq >> 1) * 16 + (qq & 1) * 8 + rq;
        float2 p0 = stats[rr], p1 = stats[64 + rr], p2 = stats[128 + rr], p3 = stats[192 + rr];
        float a1 = (p0.x + p1.x) + (p2.x + p3.x);
        float a2 = (p0.y + p1.y) + (p2.y + p3.y);
        float mu = a1 * (1.0f / 256.0f);
        rs[qq]  = rsqrtf(a2 * (1.0f / 256.0f) - mu * mu + 1e-5f);
        mrs[qq] = mu * rs[qq];
    }

    // ---- stage 2: K-chunked GEMM (4 x 64K), warp tile 32M x 64N ----
    float acc[2][8][4] = {};
    #pragma unroll
    for (int kc = 0; kc < 4; kc++) {
        CP_WAIT0();
        __syncthreads();
        issue_half(smb, tid, kc + 1);   // kc==3 issues full Wo into slot0

        const uint32_t a_addr = smb + SM_X + (uint32_t)(m_grp * 32 + (lane & 15)) * XPB
                              + ((lane >> 4) << 4) + kc * 128;
        const uint32_t b_addr = smb + SM_W + (uint32_t)(kc & 1) * SLOTSZ
                              + (uint32_t)(lane & 15) * W2PB + ((lane >> 4) << 4) + n_grp * 128;
        #pragma unroll
        for (int k0 = 0; k0 < 64; k0 += 16) {
            uint32_t A0[4], A1[4];
            ldsm_x4(A0, a_addr + k0 * 2);
            ldsm_x4(A1, a_addr + 16 * XPB + k0 * 2);
            #pragma unroll
            for (int t = 0; t < 4; t++) {
                uint32_t B[4];
                ldsm_x4_t(B, b_addr + (uint32_t)k0 * W2PB + t * 32);
                mma16816(acc[0][2 * t],     A0, B);
                mma16816(acc[0][2 * t + 1], A0, B + 2);
                mma16816(acc[1][2 * t],     A1, B);
                mma16816(acc[1][2 * t + 1], A1, B + 2);
            }
        }
    }
    CP_WAIT0();
    __syncthreads();   // Wo in slot0; ALL warps past kc3 GEMM (X & slot1 now free)

    // ---- epilogue -> outr (fp16 fragments, usable directly as mma A-operand) ----
    uint32_t outr[2][2][8];
    #pragma unroll
    for (int mi = 0; mi < 2; mi++) {
        #pragma unroll
        for (int j = 0; j < 8; j++) {
            const int cc = n_grp * 64 + j * 8 + 2 * (lane & 3);
            float2 dv = __ldg((const float2*)(g_d2 + cc));
            float2 ev = __ldg((const float2*)(g_e2 + cc));
            float x0 = gelu_exact(fmaf(rs[mi * 2], acc[mi][j][0], fmaf(-mrs[mi * 2], dv.x, ev.x)));
            float x1 = gelu_exact(fmaf(rs[mi * 2], acc[mi][j][1], fmaf(-mrs[mi * 2], dv.y, ev.y)));
            float x2 = gelu_exact(fmaf(rs[mi * 2 + 1], acc[mi][j][2], fmaf(-mrs[mi * 2 + 1], dv.x, ev.x)));
            float x3 = gelu_exact(fmaf(rs[mi * 2 + 1], acc[mi][j][3], fmaf(-mrs[mi * 2 + 1], dv.y, ev.y)));
            outr[mi][0][j] = pk(x0, x1);
            outr[mi][1][j] = pk(x2, x3);
        }
    }

    // ---- partial logits from registers: PL = y2(frag) @ Wo[k = n_grp*64..+64] ----
    float PL[2][8][4] = {};
    {
        const uint32_t wo_base = smb + SM_W
                               + (uint32_t)(n_grp * 64 + (lane & 15)) * WPB + ((lane >> 4) << 4);
        #pragma unroll
        for (int t = 0; t < 4; t++) {
            #pragma unroll
            for (int v = 0; v < 4; v++) {
                uint32_t B[4];
                ldsm_x4_t(B, wo_base + (uint32_t)(t * 16) * WPB + v * 32);
                #pragma unroll
                for (int mi = 0; mi < 2; mi++) {
                    uint32_t A[4] = { outr[mi][0][2 * t],     outr[mi][1][2 * t],
                                      outr[mi][0][2 * t + 1], outr[mi][1][2 * t + 1] };
                    mma16816(PL[mi][2 * v],     A, B);
                    mma16816(PL[mi][2 * v + 1], A, B + 2);
                }
            }
        }
    }

    // ---- store partials: P[n_grp][64 rows][64 vocab] fp32 ----
    {
        const uint32_t pofs = (n_grp == 0) ? P_OFF0 : (n_grp == 1) ? P_OFF1
                            : (n_grp == 2) ? P_OFF2 : P_OFF3;
        #pragma unroll
        for (int mi = 0; mi < 2; mi++) {
            const int row0 = m_grp * 32 + mi * 16 + rq;
            #pragma unroll
            for (int u = 0; u < 8; u++) {
                const int col = u * 8 + 2 * (lane & 3);
                *(float2*)(sm + pofs + ((uint32_t)row0 * 64 + col) * 4) =
                    make_float2(PL[mi][u][0], PL[mi][u][1]);
                *(float2*)(sm + pofs + ((uint32_t)(row0 + 8) * 64 + col) * 4) =
                    make_float2(PL[mi][u][2], PL[mi][u][3]);
            }
        }
    }
    __syncthreads();   // partials visible

    // ---- softmax: quad per row (thread = 16 vocab), sum 4 partials ----
    {
        const int rr = tid >> 2, qq = tid & 3;
        const uint32_t rofs = ((uint32_t)rr * 64 + qq * 16) * 4;
        float4 v[4];
        #pragma unroll
        for (int i = 0; i < 4; i++) {
            float4 a = *(const float4*)(sm + P_OFF0 + rofs + i * 16);
            float4 b = *(const float4*)(sm + P_OFF1 + rofs + i * 16);
            float4 c = *(const float4*)(sm + P_OFF2 + rofs + i * 16);
            float4 d = *(const float4*)(sm + P_OFF3 + rofs + i * 16);
            v[i].x = (a.x + b.x) + (c.x + d.x);
            v[i].y = (a.y + b.y) + (c.y + d.y);
            v[i].z = (a.z + b.z) + (c.z + d.z);
            v[i].w = (a.w + b.w) + (c.w + d.w);
        }
        float mx = -1e30f;
        #pragma unroll
        for (int i = 0; i < 4; i++)
            mx = fmaxf(mx, fmaxf(fmaxf(v[i].x, v[i].y), fmaxf(v[i].z, v[i].w)));
        mx = fmaxf(mx, __shfl_xor_sync(0xffffffffu, mx, 1));
        mx = fmaxf(mx, __shfl_xor_sync(0xffffffffu, mx, 2));
        float s = 0.f;
        #pragma unroll
        for (int i = 0; i < 4; i++) {
            v[i].x = __expf(v[i].x - mx); v[i].y = __expf(v[i].y - mx);
            v[i].z = __expf(v[i].z - mx); v[i].w = __expf(v[i].w - mx);
            s += (v[i].x + v[i].y) + (v[i].z + v[i].w);
        }
        s += __shfl_xor_sync(0xffffffffu, s, 1);
        s += __shfl_xor_sync(0xffffffffu, s, 2);
        const float inv = 1.0f / s;
        float4* orow = (float4*)(out + (size_t)(gr0 + rr) * VOC + qq * 16);
        #pragma unroll
        for (int i = 0; i < 4; i++) {
            v[i].x *= inv; v[i].y *= inv; v[i].z *= inv; v[i].w *= inv;
            orow[i] = v[i];
        }
    }
}

// ---------------- harness entry ----------------
extern "C" void kernel_launch(void* const* d_in, const int* in_sizes, int n_in,
                              void* d_out, int out_size)
{
    const float* memory   = (const float*)d_in[0];
    const int*   feat_idx = (const int*)  d_in[1];
    const float* emb      = (const float*)d_in[2];
    const float* Wf       = (const float*)d_in[3];
    const float* bf       = (const float*)d_in[4];
    const float* lg       = (const float*)d_in[5];
    const float* lb       = (const float*)d_in[6];
    const float* W1       = (const float*)d_in[7];
    const float* b1       = (const float*)d_in[8];
    const float* W2       = (const float*)d_in[9];
    const float* b2       = (const float*)d_in[10];
    const float* Wo       = (const float*)d_in[11];
    float* out = (float*)d_out;

    cudaFuncSetAttribute(dec_main, cudaFuncAttributeMaxDynamicSharedMemorySize, SMEM_BYTES);
    cudaFuncSetAttribute(prep_FGM, cudaFuncAttributeMaxDynamicSharedMemorySize, PF_SMEM);

    prep_weights<<<832, 256>>>(Wf, W1, W2, Wo, lg);
    prep_vecs<<<8, 256>>>(W1, b1, W2, b2, lg, lb);
    prep_FGM<<<64 + NTOK / 64, 256, PF_SMEM>>>(emb, memory, bf);
    dec_main<<<GRID_M, NT, SMEM_BYTES>>>(feat_idx, out);
}

// round 14
// speedup vs baseline: 1.1126x; 1.1126x over previous
#include <cuda_runtime.h>
#include <cuda_fp16.h>
#include <math.h>
#include <stdint.h>

// ---------------- problem constants ----------------
#define NROWS   253952      // B*S*N = 16*512*31
#define DM      256
#define VOC     64
#define NN      31
#define VE      4096
#define NTOK    8192        // B*S
#define TILE_M  64
#define GRID_M  (NROWS / TILE_M)   // 3968
#define NT      256

// ---------------- smem layout: main kernel (R11-verified) ----------------
#define XPB     528           // activation row pitch (33*16 -> conflict-free ldsm)
#define WPB     272           // weight slot row pitch (17*16)
#define SLOTSZ  34816         // 128 k-rows * 272
#define PPB     272           // logits row pitch

#define SM_X    0             // 64*528 = 33792
#define SM_W    33792         // 2 slots -> 103424
#define SM_LG   SM_W          // logits reuse slot area
#define SM_ST   103424        // float2 [2 parity][4 slot][64 rows] = 4096
#define SMEM_BYTES 107520     // 2 CTAs/SM

// ---------------- smem layout: prep_FGM ----------------
#define PF_SMA  0
#define PF_SMW  33792
#define PF_SMF  70656
#define PF_SMEM 104448

// ---------------- prepped device globals ----------------
__device__ __align__(16) __half g_wf[65536];        // Wf fp16  [k][n]
__device__ __align__(16) __half g_w1g[65536];       // lg[k]*W1 [k][n]
__device__ __align__(16) __half g_w2g[65536];       // lg[k]*W2 [k][n]
__device__ __align__(16) __half g_wo[16384];        // W_out    [k][64]
__device__ __align__(16) __half g_F[VE * 256];      // F[e] = gelu(emb[e]@Wf + bf)
__device__ __align__(16) __half g_G1h[VE * 256];    // F[e] @ W1g   (fp16)
__device__ __align__(16) __half g_M1h[NTOK * 256];  // mh[tok] @ W1g (fp16)
__device__ __align__(16) __half g_mh[NTOK * 256];   // fp16 memory copy
__device__ __align__(16) float2 g_SF[VE];           // (sum F, sum F^2)
__device__ __align__(16) float2 g_SM[NTOK];         // (sum mh, sum mh^2)
__device__ float g_d1[256], g_e1[256], g_d2[256], g_e2[256];

// ---------------- PTX helpers ----------------
__device__ __forceinline__ uint32_t smem_u32_of(const void* p) {
    uint32_t a;
    asm("{ .reg .u64 t; cvta.to.shared.u64 t, %1; cvt.u32.u64 %0, t; }" : "=r"(a) : "l"(p));
    return a;
}
__device__ __forceinline__ void ldsm_x4(uint32_t* r, uint32_t addr) {
    asm volatile("ldmatrix.sync.aligned.m8n8.x4.shared.b16 {%0,%1,%2,%3}, [%4];"
        : "=r"(r[0]), "=r"(r[1]), "=r"(r[2]), "=r"(r[3]) : "r"(addr));
}
__device__ __forceinline__ void ldsm_x4_t(uint32_t* r, uint32_t addr) {
    asm volatile("ldmatrix.sync.aligned.m8n8.x4.trans.shared.b16 {%0,%1,%2,%3}, [%4];"
        : "=r"(r[0]), "=r"(r[1]), "=r"(r[2]), "=r"(r[3]) : "r"(addr));
}
__device__ __forceinline__ void mma16816(float* d, const uint32_t* a, const uint32_t* b) {
    asm volatile("mma.sync.aligned.m16n8k16.row.col.f32.f16.f16.f32 "
        "{%0,%1,%2,%3}, {%4,%5,%6,%7}, {%8,%9}, {%0,%1,%2,%3};"
        : "+f"(d[0]), "+f"(d[1]), "+f"(d[2]), "+f"(d[3])
        : "r"(a[0]), "r"(a[1]), "r"(a[2]), "r"(a[3]), "r"(b[0]), "r"(b[1]));
}
#define CP_ASYNC16(dst, src) \
    asm volatile("cp.async.cg.shared.global [%0], [%1], 16;" :: "r"(dst), "l"(src) : "memory")
#define CP_COMMIT() asm volatile("cp.async.commit_group;" ::: "memory")
#define CP_WAIT0()  asm volatile("cp.async.wait_group 0;" ::: "memory")

// ---------------- math helpers ----------------
__device__ __forceinline__ float gelu_exact(float x) {
    return 0.5f * x * (1.0f + erff(x * 0.70710678118654752f));
}
__device__ __forceinline__ uint32_t pk(float a, float b) {
    __half2 h = __floats2half2_rn(a, b);
    return *reinterpret_cast<uint32_t*>(&h);
}
__device__ __forceinline__ float2 unpk(uint32_t u) {
    __half2 h = *reinterpret_cast<__half2*>(&u);
    return __half22float2(h);
}
__device__ __forceinline__ float2 addh2(uint32_t a, uint32_t b) {
    __half2 ha = *reinterpret_cast<__half2*>(&a);
    __half2 hb = *reinterpret_cast<__half2*>(&b);
    return __half22float2(__hadd2(ha, hb));
}

// ---------------- prep: weights + folded-LN vectors (merged) ----------------
// blocks 0..831: fp16 weight conversion; blocks 832..839: d/e vectors
__global__ void prep_weights(const float* __restrict__ Wf, const float* __restrict__ W1,
                             const float* __restrict__ W2, const float* __restrict__ Wo,
                             const float* __restrict__ lg, const float* __restrict__ lb,
                             const float* __restrict__ b1, const float* __restrict__ b2) {
    if (blockIdx.x < 832) {
        int idx = blockIdx.x * blockDim.x + threadIdx.x;   // 832*256
        if (idx < 65536) {
            g_wf[idx] = __float2half_rn(Wf[idx]);
        } else if (idx < 131072) {
            int e = idx - 65536;
            g_w1g[e] = __float2half_rn(lg[e >> 8] * W1[e]);
        } else if (idx < 196608) {
            int e = idx - 131072;
            g_w2g[e] = __float2half_rn(lg[e >> 8] * W2[e]);
        } else {
            int e = idx - 196608;
            g_wo[e] = __float2half_rn(Wo[e]);
        }
    } else {
        const int tid = threadIdx.x;
        const int n  = (blockIdx.x - 832) * 32 + (tid >> 3);
        const int ks = tid & 7;
        float d1 = 0.f, e1 = 0.f, d2 = 0.f, e2 = 0.f;
        for (int k = ks * 32; k < ks * 32 + 32; k++) {
            float g = lg[k], b = lb[k];
            float w1 = W1[k * 256 + n], w2 = W2[k * 256 + n];
            d1 += g * w1; e1 += b * w1;
            d2 += g * w2; e2 += b * w2;
        }
        #pragma unroll
        for (int off = 1; off <= 4; off <<= 1) {
            d1 += __shfl_xor_sync(0xffffffffu, d1, off);
            e1 += __shfl_xor_sync(0xffffffffu, e1, off);
            d2 += __shfl_xor_sync(0xffffffffu, d2, off);
            e2 += __shfl_xor_sync(0xffffffffu, e2, off);
        }
        if (ks == 0) {
            g_d1[n] = d1; g_e1[n] = e1 + b1[n];
            g_d2[n] = d2; g_e2[n] = e2 + b2[n];
        }
    }
}

// ---------------- prep_FGM (verified R11) ----------------
__global__ void __launch_bounds__(256, 1)
prep_FGM(const float* __restrict__ emb, const float* __restrict__ memory,
         const float* __restrict__ bf)
{
    extern __shared__ __align__(16) uint8_t sm[];
    const int tid = threadIdx.x, wid = tid >> 5, lane = tid & 31;
    const bool fpath = (blockIdx.x < 64);
    const int row0 = fpath ? blockIdx.x * 64 : (blockIdx.x - 64) * 64;
    const float* A = fpath ? (emb + (size_t)row0 * 256) : (memory + (size_t)row0 * 256);
    const uint32_t smb = smem_u32_of(sm);

    for (int q = tid; q < 64 * 8; q += 256) {
        int row = q >> 3, c32 = (q & 7) << 5;
        const float4* src = (const float4*)(A + (size_t)row * 256 + c32);
        uint4* dst = (uint4*)(sm + PF_SMA + (uint32_t)row * XPB + c32 * 2);
        #pragma unroll
        for (int u = 0; u < 4; u++) {
            float4 f0 = __ldg(src + 2 * u);
            float4 f1 = __ldg(src + 2 * u + 1);
            uint4 p;
            p.x = pk(f0.x, f0.y); p.y = pk(f0.z, f0.w);
            p.z = pk(f1.x, f1.y); p.w = pk(f1.z, f1.w);
            dst[u] = p;
            if (!fpath)
                *(uint4*)(g_mh + (size_t)(row0 + row) * 256 + c32 + u * 8) = p;
        }
    }

    const int m_grp = wid >> 1, n_grp = wid & 1;
    const __half* W1p = fpath ? g_wf : g_w1g;

    for (int j0 = 0; j0 < 256; j0 += 64) {
        __syncthreads();
        #pragma unroll
        for (int i = tid; i < 2048; i += 256) {
            int k = i >> 3, c = i & 7;
            CP_ASYNC16(smb + PF_SMW + k * 144 + (c << 4),
                       (const uint8_t*)(W1p + (size_t)k * 256 + j0) + (c << 4));
        }
        CP_COMMIT();
        CP_WAIT0();
        __syncthreads();

        const uint32_t a_addr = smb + PF_SMA + (uint32_t)(m_grp * 16 + (lane & 15)) * XPB + ((lane >> 4) << 4);
        const uint32_t b_addr = smb + PF_SMW + (uint32_t)(lane & 15) * 144 + ((lane >> 4) << 4) + n_grp * 64;
        float acc[4][4] = {};
        #pragma unroll
        for (int k0 = 0; k0 < 256; k0 += 16) {
            uint32_t Ar[4], B0[4], B1[4];
            ldsm_x4(Ar, a_addr + k0 * 2);
            ldsm_x4_t(B0, b_addr + (uint32_t)k0 * 144);
            ldsm_x4_t(B1, b_addr + (uint32_t)k0 * 144 + 32);
            mma16816(acc[0], Ar, B0); mma16816(acc[1], Ar, B0 + 2);
            mma16816(acc[2], Ar, B1); mma16816(acc[3], Ar, B1 + 2);
        }
        const int rlo = m_grp * 16 + (lane >> 2), rhi = rlo + 8;
        #pragma unroll
        for (int v = 0; v < 4; v++) {
            const int col = j0 + n_grp * 32 + v * 8 + 2 * (lane & 3);
            if (fpath) {
                float b0 = __ldg(bf + col), b1v = __ldg(bf + col + 1);
                uint32_t plo = pk(gelu_exact(acc[v][0] + b0), gelu_exact(acc[v][1] + b1v));
                uint32_t phi = pk(gelu_exact(acc[v][2] + b0), gelu_exact(acc[v][3] + b1v));
                *(uint32_t*)(g_F + (size_t)(row0 + rlo) * 256 + col) = plo;
                *(uint32_t*)(g_F + (size_t)(row0 + rhi) * 256 + col) = phi;
                *(uint32_t*)(sm + PF_SMF + (uint32_t)rlo * XPB + col * 2) = plo;
                *(uint32_t*)(sm + PF_SMF + (uint32_t)rhi * XPB + col * 2) = phi;
            } else {
                *(uint32_t*)(g_M1h + (size_t)(row0 + rlo) * 256 + col) = pk(acc[v][0], acc[v][1]);
                *(uint32_t*)(g_M1h + (size_t)(row0 + rhi) * 256 + col) = pk(acc[v][2], acc[v][3]);
            }
        }
    }
    __syncthreads();

    {
        const int rr = tid >> 2, qq = tid & 3;
        const uint32_t base = fpath ? PF_SMF : PF_SMA;
        const uint4* rp = (const uint4*)(sm + base + (uint32_t)rr * XPB + qq * 128);
        float s1 = 0.f, s2 = 0.f;
        #pragma unroll
        for (int u = 0; u < 8; u++) {
            uint4 v = rp[u];
            float2 a0 = unpk(v.x), a1 = unpk(v.y), a2 = unpk(v.z), a3 = unpk(v.w);
            s1 += (a0.x + a0.y) + (a1.x + a1.y) + (a2.x + a2.y) + (a3.x + a3.y);
            s2 += a0.x*a0.x + a0.y*a0.y + a1.x*a1.x + a1.y*a1.y
                + a2.x*a2.x + a2.y*a2.y + a3.x*a3.x + a3.y*a3.y;
        }
        s1 += __shfl_xor_sync(0xffffffffu, s1, 1);
        s2 += __shfl_xor_sync(0xffffffffu, s2, 1);
        s1 += __shfl_xor_sync(0xffffffffu, s1, 2);
        s2 += __shfl_xor_sync(0xffffffffu, s2, 2);
        if (qq == 0) {
            if (fpath) g_SF[row0 + rr] = make_float2(s1, s2);
            else       g_SM[row0 + rr] = make_float2(s1, s2);
        }
    }
    if (!fpath) return;

    for (int j0 = 0; j0 < 256; j0 += 64) {
        __syncthreads();
        #pragma unroll
        for (int i = tid; i < 2048; i += 256) {
            int k = i >> 3, c = i & 7;
            CP_ASYNC16(smb + PF_SMW + k * 144 + (c << 4),
                       (const uint8_t*)(g_w1g + (size_t)k * 256 + j0) + (c << 4));
        }
        CP_COMMIT();
        CP_WAIT0();
        __syncthreads();

        const uint32_t a_addr = smb + PF_SMF + (uint32_t)(m_grp * 16 + (lane & 15)) * XPB + ((lane >> 4) << 4);
        const uint32_t b_addr = smb + PF_SMW + (uint32_t)(lane & 15) * 144 + ((lane >> 4) << 4) + n_grp * 64;
        float acc[4][4] = {};
        #pragma unroll
        for (int k0 = 0; k0 < 256; k0 += 16) {
            uint32_t Ar[4], B0[4], B1[4];
            ldsm_x4(Ar, a_addr + k0 * 2);
            ldsm_x4_t(B0, b_addr + (uint32_t)k0 * 144);
            ldsm_x4_t(B1, b_addr + (uint32_t)k0 * 144 + 32);
            mma16816(acc[0], Ar, B0); mma16816(acc[1], Ar, B0 + 2);
            mma16816(acc[2], Ar, B1); mma16816(acc[3], Ar, B1 + 2);
        }
        const int rlo = m_grp * 16 + (lane >> 2), rhi = rlo + 8;
        #pragma unroll
        for (int v = 0; v < 4; v++) {
            const int col = j0 + n_grp * 32 + v * 8 + 2 * (lane & 3);
            *(uint32_t*)(g_G1h + (size_t)(row0 + rlo) * 256 + col) = pk(acc[v][0], acc[v][1]);
            *(uint32_t*)(g_G1h + (size_t)(row0 + rhi) * 256 + col) = pk(acc[v][2], acc[v][3]);
        }
    }
}

// ---------------- main kernel: half-chunk issue (R11) ----------------
// h 0..3: W2g (cols ((h>>1)&1)*128, K-half h&1); h 4,5: Wo K-halves (64 cols)
__device__ __forceinline__ void issue_half(uint32_t smb, int tid, int h) {
    if (h > 5) return;
    uint32_t dst = smb + SM_W + (uint32_t)(h & 1) * SLOTSZ;
    if (h < 4) {
        const __half* src = g_w2g + (size_t)((h & 1) * 128) * 256 + ((h >> 1) & 1) * 128;
        #pragma unroll
        for (int i = tid; i < 2048; i += NT) {
            int k = i >> 4, ch = i & 15;
            CP_ASYNC16(dst + k * WPB + (ch << 4),
                       (const uint8_t*)(src + (size_t)k * 256) + (ch << 4));
        }
    } else {
        const __half* src = g_wo + (size_t)((h & 1) * 128) * 64;
        #pragma unroll
        for (int i = tid; i < 1024; i += NT) {
            int k = i >> 3, ch = i & 7;
            CP_ASYNC16(dst + k * WPB + (ch << 4),
                       (const uint8_t*)(src + (size_t)k * 64) + (ch << 4));
        }
    }
    CP_COMMIT();
}

// ---------------- main fused kernel (R11-verified structure) ----------------
__global__ void __launch_bounds__(NT, 2)
dec_main(const int* __restrict__ fidx, float* __restrict__ out)
{
    extern __shared__ __align__(16) uint8_t sm[];
    const int tid   = threadIdx.x;
    const int wid   = tid >> 5;
    const int lane  = tid & 31;
    const int m_grp = wid & 1;
    const int n_grp = wid >> 1;
    const int gr0   = blockIdx.x * TILE_M;
    const uint32_t smb = smem_u32_of(sm);
    float2* stats = (float2*)(sm + SM_ST);

    issue_half(smb, tid, 0);

    // ---- fused gather: dot + folded-LN + y1 -> X smem; stats(y1) -> parity 1 ----
    const int r = tid >> 2, q = tid & 3;
    const int e = __ldg(fidx + gr0 + r);
    const int tok = (gr0 + r) / NN;
    {
        const uint4* Fp = (const uint4*)(g_F  + (size_t)e   * DM + q * 64);
        const uint4* Mp = (const uint4*)(g_mh + (size_t)tok * DM + q * 64);
        float dot = 0.f;
        #pragma unroll
        for (int u = 0; u < 8; u++) {
            uint4 fv = __ldg(Fp + u);
            uint4 mv = __ldg(Mp + u);
            float2 f0 = unpk(fv.x), f1 = unpk(fv.y), f2 = unpk(fv.z), f3 = unpk(fv.w);
            float2 m0 = unpk(mv.x), m1 = unpk(mv.y), m2 = unpk(mv.z), m3 = unpk(mv.w);
            dot += f0.x*m0.x + f0.y*m0.y + f1.x*m1.x + f1.y*m1.y
                 + f2.x*m2.x + f2.y*m2.y + f3.x*m3.x + f3.y*m3.y;
        }
        dot += __shfl_xor_sync(0xffffffffu, dot, 1);
        dot += __shfl_xor_sync(0xffffffffu, dot, 2);

        float2 sf  = __ldg(&g_SF[e]);
        float2 smv = __ldg(&g_SM[tok]);
        const float s1x = sf.x + smv.x;
        const float s2x = sf.y + smv.y + 2.0f * dot;
        const float mu  = s1x * (1.0f / 256.0f);
        const float rsx = rsqrtf(s2x * (1.0f / 256.0f) - mu * mu + 1e-5f);
        const float nmr = -mu * rsx;

        const uint4* Gp = (const uint4*)(g_G1h + (size_t)e   * DM + q * 64);
        const uint4* Np = (const uint4*)(g_M1h + (size_t)tok * DM + q * 64);
        float s1 = 0.f, s2 = 0.f;
        #pragma unroll
        for (int u = 0; u < 8; u++) {
            const int c = q * 64 + u * 8;
            uint4 gv = __ldg(Gp + u);
            uint4 nv = __ldg(Np + u);
            float2 z0 = addh2(gv.x, nv.x), z1 = addh2(gv.y, nv.y);
            float2 z2 = addh2(gv.z, nv.z), z3 = addh2(gv.w, nv.w);
            float4 da = __ldg((const float4*)(g_d1 + c)), db = __ldg((const float4*)(g_d1 + c + 4));
            float4 ea = __ldg((const float4*)(g_e1 + c)), eb = __ldg((const float4*)(g_e1 + c + 4));
            float y0 = gelu_exact(fmaf(rsx, z0.x, fmaf(nmr, da.x, ea.x)));
            float y1 = gelu_exact(fmaf(rsx, z0.y, fmaf(nmr, da.y, ea.y)));
            float y2 = gelu_exact(fmaf(rsx, z1.x, fmaf(nmr, da.z, ea.z)));
            float y3 = gelu_exact(fmaf(rsx, z1.y, fmaf(nmr, da.w, ea.w)));
            float y4 = gelu_exact(fmaf(rsx, z2.x, fmaf(nmr, db.x, eb.x)));
            float y5 = gelu_exact(fmaf(rsx, z2.y, fmaf(nmr, db.y, eb.y)));
            float y6 = gelu_exact(fmaf(rsx, z3.x, fmaf(nmr, db.z, eb.z)));
            float y7 = gelu_exact(fmaf(rsx, z3.y, fmaf(nmr, db.w, eb.w)));
            s1 += (y0 + y1) + (y2 + y3) + (y4 + y5) + (y6 + y7);
            s2 += y0*y0 + y1*y1 + y2*y2 + y3*y3 + y4*y4 + y5*y5 + y6*y6 + y7*y7;
            uint4 p;
            p.x = pk(y0, y1); p.y = pk(y2, y3); p.z = pk(y4, y5); p.w = pk(y6, y7);
            *(uint4*)(sm + SM_X + (uint32_t)r * XPB + c * 2) = p;
        }
        stats[256 + q * 64 + r] = make_float2(s1, s2);   // parity 1
    }
    __syncthreads();

    // ---- stage 2: y2 = gelu(rs2*(y1@W2g) - mu2*rs2*d2 + e2), halves h0..3 ----
    {
        const int rq = lane >> 2;
        float rs[4], mrs[4];
        #pragma unroll
        for (int qq = 0; qq < 4; qq++) {
            int rr = m_grp * 32 + (qq >> 1) * 16 + (qq & 1) * 8 + rq;
            const float2* stRd = stats + 256;
            float2 p0 = stRd[rr], p1 = stRd[64 + rr], p2 = stRd[128 + rr], p3 = stRd[192 + rr];
            float a1 = (p0.x + p1.x) + (p2.x + p3.x);
            float a2 = (p0.y + p1.y) + (p2.y + p3.y);
            float mu = a1 * (1.0f / 256.0f);
            rs[qq]  = rsqrtf(a2 * (1.0f / 256.0f) - mu * mu + 1e-5f);
            mrs[qq] = mu * rs[qq];
        }

        uint32_t outr[2][2][2][4];
        #pragma unroll
        for (int g = 0; g < 2; g++) {
            float acc[2][4][4] = {};
            #pragma unroll
            for (int kh = 0; kh < 2; kh++) {
                const int h = 2 * g + kh;
                CP_WAIT0();
                __syncthreads();
                issue_half(smb, tid, h + 1);

                const uint32_t a_addr = smb + SM_X + (uint32_t)(m_grp * 32 + (lane & 15)) * XPB
                                      + ((lane >> 4) << 4) + kh * 256;
                const uint32_t b_addr = smb + SM_W + (uint32_t)(h & 1) * SLOTSZ
                                      + (uint32_t)(lane & 15) * WPB + ((lane >> 4) << 4) + n_grp * 64;
                #pragma unroll
                for (int k0 = 0; k0 < 128; k0 += 16) {
                    uint32_t A0[4], A1[4], B0[4], B1[4];
                    ldsm_x4(A0, a_addr + k0 * 2);
                    ldsm_x4(A1, a_addr + 16 * XPB + k0 * 2);
                    ldsm_x4_t(B0, b_addr + (uint32_t)k0 * WPB);
                    ldsm_x4_t(B1, b_addr + (uint32_t)k0 * WPB + 32);
                    mma16816(acc[0][0], A0, B0); mma16816(acc[0][1], A0, B0 + 2);
                    mma16816(acc[0][2], A0, B1); mma16816(acc[0][3], A0, B1 + 2);
                    mma16816(acc[1][0], A1, B0); mma16816(acc[1][1], A1, B0 + 2);
                    mma16816(acc[1][2], A1, B1); mma16816(acc[1][3], A1, B1 + 2);
                }
            }
            const int cbase = g * 128 + n_grp * 32 + 2 * (lane & 3);
            #pragma unroll
            for (int mi = 0; mi < 2; mi++) {
                #pragma unroll
                for (int v = 0; v < 4; v++) {
                    const int cc = cbase + v * 8;
                    float2 dv = __ldg((const float2*)(g_d2 + cc));
                    float2 ev = __ldg((const float2*)(g_e2 + cc));
                    float x0 = gelu_exact(fmaf(rs[mi * 2], acc[mi][v][0], fmaf(-mrs[mi * 2], dv.x, ev.x)));
                    float x1 = gelu_exact(fmaf(rs[mi * 2], acc[mi][v][1], fmaf(-mrs[mi * 2], dv.y, ev.y)));
                    float x2 = gelu_exact(fmaf(rs[mi * 2 + 1], acc[mi][v][2], fmaf(-mrs[mi * 2 + 1], dv.x, ev.x)));
                    float x3 = gelu_exact(fmaf(rs[mi * 2 + 1], acc[mi][v][3], fmaf(-mrs[mi * 2 + 1], dv.y, ev.y)));
                    outr[g][mi][0][v] = pk(x0, x1);
                    outr[g][mi][1][v] = pk(x2, x3);
                }
            }
        }
        __syncthreads();
        #pragma unroll
        for (int g = 0; g < 2; g++) {
            const int cbase = g * 128 + n_grp * 32 + 2 * (lane & 3);
            #pragma unroll
            for (int mi = 0; mi < 2; mi++) {
                const int rA = m_grp * 32 + mi * 16 + rq;
                #pragma unroll
                for (int v = 0; v < 4; v++) {
                    const int cc = cbase + v * 8;
                    *(uint32_t*)(sm + SM_X + (uint32_t)rA * XPB + cc * 2)       = outr[g][mi][0][v];
                    *(uint32_t*)(sm + SM_X + (uint32_t)(rA + 8) * XPB + cc * 2) = outr[g][mi][1][v];
                }
            }
        }
    }

    // ---- logits: 64x64, Wo halves h4,h5; warp tile 32M x 16N ----
    float acc[2][2][4] = {};
    #pragma unroll
    for (int kh = 0; kh < 2; kh++) {
        CP_WAIT0();
        __syncthreads();
        if (kh == 0) issue_half(smb, tid, 5);
        const uint32_t a_addr = smb + SM_X + (uint32_t)(m_grp * 32 + (lane & 15)) * XPB
                              + ((lane >> 4) << 4) + kh * 256;
        const uint32_t b_addr = smb + SM_W + (uint32_t)kh * SLOTSZ
                              + (uint32_t)(lane & 15) * WPB + ((lane >> 4) << 4) + n_grp * 32;
        #pragma unroll
        for (int k0 = 0; k0 < 128; k0 += 16) {
            uint32_t A0[4], A1[4], B0[4];
            ldsm_x4(A0, a_addr + k0 * 2);
            ldsm_x4(A1, a_addr + 16 * XPB + k0 * 2);
            ldsm_x4_t(B0, b_addr + (uint32_t)k0 * WPB);
            mma16816(acc[0][0], A0, B0); mma16816(acc[0][1], A0, B0 + 2);
            mma16816(acc[1][0], A1, B0); mma16816(acc[1][1], A1, B0 + 2);
        }
    }
    __syncthreads();

    #pragma unroll
    for (int mi = 0; mi < 2; mi++) {
        const int rlo = m_grp * 32 + mi * 16 + (lane >> 2);
        #pragma unroll
        for (int v = 0; v < 2; v++) {
            const int cc = n_grp * 16 + v * 8 + 2 * (lane & 3);
            *(float2*)(sm + SM_LG + (uint32_t)rlo * PPB + cc * 4)       = make_float2(acc[mi][v][0], acc[mi][v][1]);
            *(float2*)(sm + SM_LG + (uint32_t)(rlo + 8) * PPB + cc * 4) = make_float2(acc[mi][v][2], acc[mi][v][3]);
        }
    }
    __syncthreads();

    // ---- softmax: one thread per row ----
    if (tid < TILE_M) {
        uint8_t* rowp = sm + SM_LG + (uint32_t)tid * PPB;
        float4 v[16];
        float mx = -1e30f;
        #pragma unroll
        for (int i = 0; i < 16; i++) {
            v[i] = *(const float4*)(rowp + i * 16);
            mx = fmaxf(mx, fmaxf(fmaxf(v[i].x, v[i].y), fmaxf(v[i].z, v[i].w)));
        }
        float s = 0.f;
        #pragma unroll
        for (int i = 0; i < 16; i++) {
            v[i].x = __expf(v[i].x - mx); v[i].y = __expf(v[i].y - mx);
            v[i].z = __expf(v[i].z - mx); v[i].w = __expf(v[i].w - mx);
            s += (v[i].x + v[i].y) + (v[i].z + v[i].w);
        }
        const float inv = 1.0f / s;
        #pragma unroll
        for (int i = 0; i < 16; i++) {
            v[i].x *= inv; v[i].y *= inv; v[i].z *= inv; v[i].w *= inv;
            *(float4*)(rowp + i * 16) = v[i];
        }
    }
    __syncthreads();

    // ---- coalesced output store ----
    float* og = out + (size_t)gr0 * VOC;
    #pragma unroll
    for (int i = tid; i < TILE_M * VOC / 4; i += NT) {
        int row = i >> 4, c4 = i & 15;
        *(float4*)(og + row * VOC + c4 * 4) =
            *(const float4*)(sm + SM_LG + (uint32_t)row * PPB + c4 * 16);
    }
}

// ---------------- harness entry ----------------
extern "C" void kernel_launch(void* const* d_in, const int* in_sizes, int n_in,
                              void* d_out, int out_size)
{
    const float* memory   = (const float*)d_in[0];
    const int*   feat_idx = (const int*)  d_in[1];
    const float* emb      = (const float*)d_in[2];
    const float* Wf       = (const float*)d_in[3];
    const float* bf       = (const float*)d_in[4];
    const float* lg       = (const float*)d_in[5];
    const float* lb       = (const float*)d_in[6];
    const float* W1       = (const float*)d_in[7];
    const float* b1       = (const float*)d_in[8];
    const float* W2       = (const float*)d_in[9];
    const float* b2       = (const float*)d_in[10];
    const float* Wo       = (const float*)d_in[11];
    float* out = (float*)d_out;

    cudaFuncSetAttribute(dec_main, cudaFuncAttributeMaxDynamicSharedMemorySize, SMEM_BYTES);
    cudaFuncSetAttribute(prep_FGM, cudaFuncAttributeMaxDynamicSharedMemorySize, PF_SMEM);

    prep_weights<<<840, 256>>>(Wf, W1, W2, Wo, lg, lb, b1, b2);
    prep_FGM<<<64 + NTOK / 64, 256, PF_SMEM>>>(emb, memory, bf);
    dec_main<<<GRID_M, NT, SMEM_BYTES>>>(feat_idx, out);
}